// round 11
// baseline (speedup 1.0000x reference)
#include <cuda_runtime.h>

// y = x*2 + 5 - 3/(1+x), elementwise over 8192*8192 fp32 (64M elems).
//
// FINAL — locked after a 10-round mechanism sweep (MLP 1/4/8, 128/256-bit
// ops, cs/wt/default/evict-last policies, T=128/256/512, oversubscribed vs
// persistent grids). All sound configs land at 6.37-6.52 TB/s: the mixed
// read+write HBM3e ceiling on this part. This is the best-measured point:
//   - 4x float4 per thread, front-batched (MLP=4), 256-thread blocks,
//     16384-CTA oversubscribed grid (deep CTA pool = the memory pipeline;
//     persistent single-wave measured 13% worse).
//   - streaming cache hints (ld/st.global.cs) on pure pass-through data.
//   - __fdividef: MUFU.RCP+MUL (rel_err ~3e-8 << 1e-3 threshold).
// Measured: 81.95 us timed, 6.52 TB/s, DRAM 82.3%, rel_err 3.4e-8.

constexpr int V = 4;    // float4 per thread
constexpr int T = 256;  // threads per block

__global__ __launch_bounds__(T)
void elementwise_final_kernel(const float4* __restrict__ in,
                              float4* __restrict__ out) {
    int base = blockIdx.x * (T * V) + threadIdx.x;

    float4 v[V];
#pragma unroll
    for (int k = 0; k < V; k++) {
        v[k] = __ldcs(&in[base + k * T]);   // 4 independent LDG.E.128, front-batched
    }

#pragma unroll
    for (int k = 0; k < V; k++) {
        float4 r;
        r.x = fmaf(v[k].x, 2.0f, 5.0f) - __fdividef(3.0f, 1.0f + v[k].x);
        r.y = fmaf(v[k].y, 2.0f, 5.0f) - __fdividef(3.0f, 1.0f + v[k].y);
        r.z = fmaf(v[k].z, 2.0f, 5.0f) - __fdividef(3.0f, 1.0f + v[k].z);
        r.w = fmaf(v[k].w, 2.0f, 5.0f) - __fdividef(3.0f, 1.0f + v[k].w);
        __stcs(&out[base + k * T], r);
    }
}

extern "C" void kernel_launch(void* const* d_in, const int* in_sizes, int n_in,
                              void* d_out, int out_size) {
    const float* x = (const float*)d_in[0];
    float* y = (float*)d_out;
    int n = in_sizes[0];          // 67108864 = 8192*8192
    int n4 = n >> 2;              // 16777216 float4

    // Exact tiling: 16777216 / (256*4) = 16384 blocks, no tail.
    int blocks = n4 / (T * V);
    elementwise_final_kernel<<<blocks, T>>>(
        (const float4*)x, (float4*)y);
}